// round 5
// baseline (speedup 1.0000x reference)
#include <cuda_runtime.h>
#include <math.h>

// Problem dims
#define B 32
#define S 256
#define EHID 768
#define DHID 128
#define EMBD 200
#define VOC 32000
#define TT 96
#define NSTEP 95
#define KFC 1096    // DHID + EHID + EMBD
#define KLSTM 968   // EMBD + EHID

// Scratch (static device globals: allowed; no runtime allocation)
__device__ float g_fcwt[(size_t)KFC * VOC];   // fc_W transposed: [k][v], ~140MB
__device__ float g_enc_proj[B * S * DHID];    // 4MB, step-invariant attention term
__device__ float g_xcatT[KFC * B];            // FC input, transposed [k][b]
__device__ float g_h[2][B * DHID];            // ping-pong (k_lstm blocks race otherwise)
__device__ float g_c[B * DHID];

typedef unsigned long long ull;

// fast activations: ~1e-6 abs err (safe: min argmax gap ~7e-5; fp32 ref err 7e-7)
__device__ __forceinline__ float sigfast(float x) {
    return __fdividef(1.0f, 1.0f + __expf(-x));
}
__device__ __forceinline__ float tanhfast(float x) {
    x = fminf(fmaxf(x, -15.0f), 15.0f);          // avoid inf/inf
    float e = __expf(2.0f * x);
    return __fdividef(e - 1.0f, e + 1.0f);
}

// packed fp32x2 helpers (double-rate FFMA path; ptxas never auto-emits it)
__device__ __forceinline__ ull pk2(float lo, float hi) {
    ull r; asm("mov.b64 %0, {%1, %2};" : "=l"(r) : "f"(lo), "f"(hi)); return r;
}
__device__ __forceinline__ void upk2(ull v, float& lo, float& hi) {
    asm("mov.b64 {%0, %1}, %2;" : "=f"(lo), "=f"(hi) : "l"(v));
}
__device__ __forceinline__ void ffma2(ull& d, ull a, ull b) {
    asm("fma.rn.f32x2 %0, %1, %2, %0;" : "+l"(d) : "l"(a), "l"(b));
}

// ---------------------------------------------------------------------------
// Init: zero h (both buffers), c, and outputs[:, 0, :]
// ---------------------------------------------------------------------------
__global__ void k_init(float* __restrict__ outp) {
    int i = blockIdx.x * blockDim.x + threadIdx.x;
    if (i < B * VOC) {
        int b = i / VOC, v = i % VOC;
        outp[(size_t)b * TT * VOC + v] = 0.0f;
    }
    if (i < B * DHID) { g_h[0][i] = 0.0f; g_h[1][i] = 0.0f; g_c[i] = 0.0f; }
}

// ---------------------------------------------------------------------------
// Transpose fc_W [VOC][KFC] -> g_fcwt [KFC][VOC] (once)
// ---------------------------------------------------------------------------
__global__ void k_transpose(const float* __restrict__ W) {
    __shared__ float tile[32][33];
    int tx = threadIdx.x, ty = threadIdx.y;          // 32 x 8
    int v0 = blockIdx.x * 32, k0 = blockIdx.y * 32;
    for (int r = ty; r < 32; r += 8) {
        int k = k0 + tx;
        tile[r][tx] = (k < KFC) ? W[(size_t)(v0 + r) * KFC + k] : 0.0f;
    }
    __syncthreads();
    for (int r = ty; r < 32; r += 8) {
        int k = k0 + r;
        if (k < KFC) g_fcwt[(size_t)k * VOC + v0 + tx] = tile[tx][r];
    }
}

// ---------------------------------------------------------------------------
// enc_proj[b,s,j] = attn_b[j] + sum_k enc[b,s,k] * attn_W[128+k][j]   (once)
// ---------------------------------------------------------------------------
__global__ void __launch_bounds__(128) k_encproj(const float* __restrict__ enc,
                                                 const float* __restrict__ attn_W,
                                                 const float* __restrict__ attn_b) {
    __shared__ __align__(16) float es[32 * 8];
    int j = threadIdx.x;
    int row0 = blockIdx.x * 32;
    float acc[32];
    float bj = attn_b[j];
#pragma unroll
    for (int r = 0; r < 32; r++) acc[r] = bj;
    const float* Wenc = attn_W + DHID * DHID;

    for (int k0 = 0; k0 < EHID; k0 += 8) {
        __syncthreads();
        int i0 = j;
        es[i0] = enc[(size_t)(row0 + (i0 >> 3)) * EHID + k0 + (i0 & 7)];
        int i1 = j + 128;
        es[i1] = enc[(size_t)(row0 + (i1 >> 3)) * EHID + k0 + (i1 & 7)];
        __syncthreads();
        float w[8];
#pragma unroll
        for (int kk = 0; kk < 8; kk++) w[kk] = Wenc[(size_t)(k0 + kk) * DHID + j];
#pragma unroll
        for (int r = 0; r < 32; r++) {
            const float4* e4 = (const float4*)(es + r * 8);
            float4 e0 = e4[0], e1 = e4[1];
            acc[r] = fmaf(e0.x, w[0], acc[r]); acc[r] = fmaf(e0.y, w[1], acc[r]);
            acc[r] = fmaf(e0.z, w[2], acc[r]); acc[r] = fmaf(e0.w, w[3], acc[r]);
            acc[r] = fmaf(e1.x, w[4], acc[r]); acc[r] = fmaf(e1.y, w[5], acc[r]);
            acc[r] = fmaf(e1.z, w[6], acc[r]); acc[r] = fmaf(e1.w, w[7], acc[r]);
        }
    }
#pragma unroll
    for (int r = 0; r < 32; r++)
        g_enc_proj[(size_t)(row0 + r) * DHID + j] = acc[r];
}

// ---------------------------------------------------------------------------
// Per-step attention: hp-proj, scores (fast tanh), softmax, context, emb.
// grid = B, 512 threads. Writes g_xcatT rows 128..1095.
// ---------------------------------------------------------------------------
__global__ void __launch_bounds__(512) k_attn(
    const float* __restrict__ enc, const int* __restrict__ trg,
    const float* __restrict__ embt, const float* __restrict__ attn_W,
    const float* __restrict__ attn_v, int t)
{
    int b = blockIdx.x, tid = threadIdx.x;
    __shared__ __align__(16) float sh_h[DHID];
    __shared__ float sh_hp[DHID];
    __shared__ float sh_v[DHID];
    __shared__ float sh_a[S];
    __shared__ float sh_red[512];

    const float* hold = g_h[t & 1];
    if (tid < DHID) { sh_h[tid] = hold[b * DHID + tid]; sh_v[tid] = attn_v[tid]; }
    __syncthreads();

    // hp[j] = sum_k h[k] * attn_W[k][j]
    if (tid < DHID) {
        float acc = 0.0f;
#pragma unroll 8
        for (int k = 0; k < DHID; k++)
            acc = fmaf(sh_h[k], attn_W[k * DHID + tid], acc);
        sh_hp[tid] = acc;
    }
    __syncthreads();

    // score[s] = sum_j tanh(enc_proj + hp) * v, split over 2 j-halves
    {
        int s = tid & (S - 1);
        int j0 = (tid >> 8) * 64;
        const float* ep = g_enc_proj + ((size_t)b * S + s) * DHID + j0;
        float acc = 0.0f;
#pragma unroll 4
        for (int jj = 0; jj < 64; jj++)
            acc = fmaf(tanhfast(ep[jj] + sh_hp[j0 + jj]), sh_v[j0 + jj], acc);
        sh_red[tid] = acc;
    }
    __syncthreads();
    if (tid < S) sh_a[tid] = sh_red[tid] + sh_red[tid + S];
    __syncthreads();

    // softmax over S=256
    if (tid < S) sh_red[tid] = sh_a[tid];
    __syncthreads();
    for (int off = S / 2; off > 0; off >>= 1) {
        if (tid < off) sh_red[tid] = fmaxf(sh_red[tid], sh_red[tid + off]);
        __syncthreads();
    }
    float mx = sh_red[0];
    __syncthreads();
    if (tid < S) { float e = __expf(sh_a[tid] - mx); sh_a[tid] = e; sh_red[tid] = e; }
    __syncthreads();
    for (int off = S / 2; off > 0; off >>= 1) {
        if (tid < off) sh_red[tid] += sh_red[tid + off];
        __syncthreads();
    }
    float inv = __fdividef(1.0f, sh_red[0]);
    if (tid < S) sh_a[tid] *= inv;
    __syncthreads();

    // context: weighted[d] = sum_s a[s] * enc[b,s,d]
    const float* encb = enc + (size_t)b * S * EHID;
    for (int d = tid; d < EHID; d += 512) {
        float acc = 0.0f;
#pragma unroll 8
        for (int s = 0; s < S; s++)
            acc = fmaf(sh_a[s], encb[(size_t)s * EHID + d], acc);
        g_xcatT[(DHID + d) * B + b] = acc;           // FC x rows 128..895
    }
    // embedding gather
    int tok = trg[b * TT + t];
    if (tid < EMBD) {
        float ev = embt[(size_t)tok * EMBD + tid];
        g_xcatT[(DHID + EHID + tid) * B + b] = ev;   // rows 896..1095
    }
}

// ---------------------------------------------------------------------------
// Per-step LSTM: grid = 64 blocks (2 hid cols each), 256 threads.
// thread = (gc, b): gc=0..7 covers i/f/g/o x 2 cols; all 32 batches per warp.
// Reads W_ih once chip-wide (each block reads its 8 rows only).
// ---------------------------------------------------------------------------
__global__ void __launch_bounds__(256) k_lstm(
    const float* __restrict__ W_ih, const float* __restrict__ W_hh,
    const float* __restrict__ b_ih, const float* __restrict__ b_hh, int t)
{
    int h0 = blockIdx.x * 2;
    int tid = threadIdx.x;
    int gc = tid >> 5;                // 0..7  (q = gc>>1 gate, j = gc&1 col)
    int b  = tid & 31;
    int g  = (gc >> 1) * DHID + h0 + (gc & 1);

    __shared__ float sh_hold[32 * 129];          // old h, padded vs bank conflicts
    __shared__ float sg[8][32];

    const float* hold = g_h[t & 1];
    for (int i = tid; i < B * DHID; i += 256) {
        int bb = i >> 7, kk = i & 127;
        sh_hold[bb * 129 + kk] = hold[i];
    }
    __syncthreads();

    float a0 = b_ih[g] + b_hh[g], a1 = 0.f, a2 = 0.f, a3 = 0.f;
    const float* Wg = W_ih + (size_t)g * KLSTM;
    // emb part: x cols 0..199 live at xcatT rows 896+k
    const float* xe = g_xcatT + 896 * B + b;
#pragma unroll 2
    for (int k = 0; k < 200; k += 4) {
        float4 w = *(const float4*)(Wg + k);
        a0 = fmaf(w.x, xe[(k + 0) * B], a0);
        a1 = fmaf(w.y, xe[(k + 1) * B], a1);
        a2 = fmaf(w.z, xe[(k + 2) * B], a2);
        a3 = fmaf(w.w, xe[(k + 3) * B], a3);
    }
    // weighted part: x cols 200..967 live at xcatT rows k-72
    const float* xw = g_xcatT - 72 * B + b;
#pragma unroll 2
    for (int k = 200; k < KLSTM; k += 4) {
        float4 w = *(const float4*)(Wg + k);
        a0 = fmaf(w.x, xw[(k + 0) * B], a0);
        a1 = fmaf(w.y, xw[(k + 1) * B], a1);
        a2 = fmaf(w.z, xw[(k + 2) * B], a2);
        a3 = fmaf(w.w, xw[(k + 3) * B], a3);
    }
    // h part
    const float* Wh = W_hh + (size_t)g * DHID;
    const float* hb = sh_hold + b * 129;
#pragma unroll 4
    for (int k = 0; k < DHID; k += 4) {
        float4 w = *(const float4*)(Wh + k);
        a0 = fmaf(w.x, hb[k + 0], a0);
        a1 = fmaf(w.y, hb[k + 1], a1);
        a2 = fmaf(w.z, hb[k + 2], a2);
        a3 = fmaf(w.w, hb[k + 3], a3);
    }
    sg[gc][b] = (a0 + a1) + (a2 + a3);
    __syncthreads();

    if (gc < 2) {                                 // 64 threads: col = h0+gc
        int col = h0 + gc;
        float gi = sg[0 + gc][b], gf = sg[2 + gc][b];
        float gg = sg[4 + gc][b], go = sg[6 + gc][b];
        float c = g_c[b * DHID + col];
        c = sigfast(gf) * c + sigfast(gi) * tanhfast(gg);
        float h = sigfast(go) * tanhfast(c);
        g_c[b * DHID + col] = c;
        g_h[(t + 1) & 1][b * DHID + col] = h;     // next step's h
        g_xcatT[col * B + b] = h;                 // FC x rows 0..127
    }
}

// ---------------------------------------------------------------------------
// Per-step FC with packed fp32x2 FFMA (double-rate).
// grid = 250 blocks x 128 thr. lane -> 4 v (float4 w), warp -> 8 batches.
// Per k per warp: 1 LDG.128 (w, streaming) + 2 LDG.128 (x pairs, uniform)
//                 + 4 dup-packs + 16 FFMA2 (= 64 MACs).
// ---------------------------------------------------------------------------
__global__ void __launch_bounds__(128) k_fc(const float* __restrict__ fc_b,
                                            float* __restrict__ outp, int t) {
    int lane = threadIdx.x & 31;
    int wrp  = threadIdx.x >> 5;
    int v0 = blockIdx.x * 128 + lane * 4;
    int b0 = wrp * 8;

    ull acc[16];
#pragma unroll
    for (int i = 0; i < 16; i++) acc[i] = 0ull;

    const float* wp = g_fcwt + v0;
    const char* xbase = (const char*)(g_xcatT + b0);

#pragma unroll 4
    for (int k = 0; k < KFC; k++) {
        float4 wv = __ldcs((const float4*)(wp + (size_t)k * VOC));
        const ulonglong2* xp = (const ulonglong2*)(xbase + (size_t)k * (B * 4));
        ulonglong2 xA = __ldg(xp);          // pairs (b0,b1),(b2,b3)
        ulonglong2 xB = __ldg(xp + 1);      // pairs (b4,b5),(b6,b7)
        ull w0 = pk2(wv.x, wv.x), w1 = pk2(wv.y, wv.y);
        ull w2 = pk2(wv.z, wv.z), w3 = pk2(wv.w, wv.w);
        ffma2(acc[ 0], w0, xA.x); ffma2(acc[ 1], w0, xA.y);
        ffma2(acc[ 2], w0, xB.x); ffma2(acc[ 3], w0, xB.y);
        ffma2(acc[ 4], w1, xA.x); ffma2(acc[ 5], w1, xA.y);
        ffma2(acc[ 6], w1, xB.x); ffma2(acc[ 7], w1, xB.y);
        ffma2(acc[ 8], w2, xA.x); ffma2(acc[ 9], w2, xA.y);
        ffma2(acc[10], w2, xB.x); ffma2(acc[11], w2, xB.y);
        ffma2(acc[12], w3, xA.x); ffma2(acc[13], w3, xA.y);
        ffma2(acc[14], w3, xB.x); ffma2(acc[15], w3, xB.y);
    }

    float4 bias = *(const float4*)(fc_b + v0);
    float* obase = outp + (size_t)(t + 1) * VOC + v0;
    const size_t bs = (size_t)TT * VOC;
#pragma unroll
    for (int p = 0; p < 4; p++) {
        float x0, y0, x1, y1, x2, y2, x3, y3;
        upk2(acc[0 + p], x0, y0);   // v0+0, pair p
        upk2(acc[4 + p], x1, y1);   // v0+1
        upk2(acc[8 + p], x2, y2);   // v0+2
        upk2(acc[12 + p], x3, y3);  // v0+3
        int bA = b0 + 2 * p, bB = bA + 1;
        float4 oA = make_float4(x0 + bias.x, x1 + bias.y, x2 + bias.z, x3 + bias.w);
        float4 oB = make_float4(y0 + bias.x, y1 + bias.y, y2 + bias.z, y3 + bias.w);
        *(float4*)(obase + (size_t)bA * bs) = oA;
        *(float4*)(obase + (size_t)bB * bs) = oB;
    }
}

// ---------------------------------------------------------------------------
// Epilogue: argmax over V per (b,t) row
// ---------------------------------------------------------------------------
__global__ void __launch_bounds__(256) k_argmax(const float* __restrict__ outp,
                                                float* __restrict__ tokout) {
    int row = blockIdx.x;
    const float* p = outp + (size_t)row * VOC;
    int tid = threadIdx.x;
    float best = -1e30f;
    int bi = VOC;
    for (int i = tid; i < VOC; i += 256) {
        float vv = p[i];
        if (vv > best || (vv == best && i < bi)) { best = vv; bi = i; }
    }
    __shared__ float sv[256];
    __shared__ int si[256];
    sv[tid] = best; si[tid] = bi;
    __syncthreads();
    for (int off = 128; off > 0; off >>= 1) {
        if (tid < off) {
            float ov = sv[tid + off]; int oi = si[tid + off];
            if (ov > sv[tid] || (ov == sv[tid] && oi < si[tid])) { sv[tid] = ov; si[tid] = oi; }
        }
        __syncthreads();
    }
    if (tid == 0) tokout[row] = (float)si[0];
}

// ---------------------------------------------------------------------------
extern "C" void kernel_launch(void* const* d_in, const int* in_sizes, int n_in,
                              void* d_out, int out_size) {
    const float* enc    = (const float*)d_in[0];
    const int*   trg    = (const int*)d_in[1];
    const float* embt   = (const float*)d_in[2];
    const float* attn_W = (const float*)d_in[3];
    const float* attn_v = (const float*)d_in[5];
    const float* W_ih   = (const float*)d_in[6];
    const float* W_hh   = (const float*)d_in[7];
    const float* b_ih   = (const float*)d_in[8];
    const float* b_hh   = (const float*)d_in[9];
    const float* fc_W   = (const float*)d_in[10];
    const float* fc_b   = (const float*)d_in[11];
    const float* attn_b = (const float*)d_in[4];
    float* outp = (float*)d_out;
    (void)in_sizes; (void)n_in;

    k_init<<<(B * VOC + 255) / 256, 256>>>(outp);
    k_transpose<<<dim3(VOC / 32, (KFC + 31) / 32), dim3(32, 8)>>>(fc_W);
    k_encproj<<<(B * S) / 32, 128>>>(enc, attn_W, attn_b);

    for (int t = 0; t < NSTEP; t++) {
        k_attn<<<B, 512>>>(enc, trg, embt, attn_W, attn_v, t);
        k_lstm<<<DHID / 2, 256>>>(W_ih, W_hh, b_ih, b_hh, t);
        k_fc<<<VOC / 128, 128>>>(fc_b, outp, t);
    }

    long long need = (long long)B * TT * VOC + (long long)B * TT;
    if ((long long)out_size >= need) {
        k_argmax<<<B * TT, 256>>>(outp, outp + (size_t)B * TT * VOC);
    }
}

// round 6
// speedup vs baseline: 1.0593x; 1.0593x over previous
#include <cuda_runtime.h>
#include <math.h>

// Problem dims
#define B 32
#define S 256
#define EHID 768
#define DHID 128
#define EMBD 200
#define VOC 32000
#define TT 96
#define NSTEP 95
#define KFC 1096    // DHID + EHID + EMBD
#define KLSTM 968   // EMBD + EHID

// Scratch (static device globals: allowed; no runtime allocation)
__device__ float g_fcwt[(size_t)KFC * VOC];   // fc_W transposed: [k][v], ~140MB
__device__ float g_enc_proj[B * S * DHID];    // 4MB, step-invariant attention term
__device__ float g_xcatT[KFC * B];            // FC input, transposed [k][b]
__device__ float g_attw[B * S];               // softmax attention weights
__device__ float g_h[2][B * DHID];            // ping-pong across steps
__device__ float g_c[B * DHID];

// fast activations (validated R4: rel_err stayed 7e-7)
__device__ __forceinline__ float sigfast(float x) {
    return __fdividef(1.0f, 1.0f + __expf(-x));
}
__device__ __forceinline__ float tanhfast(float x) {
    x = fminf(fmaxf(x, -15.0f), 15.0f);
    float e = __expf(2.0f * x);
    return __fdividef(e - 1.0f, e + 1.0f);
}

// ---------------------------------------------------------------------------
// Init: zero h (both buffers), c, and outputs[:, 0, :]
// ---------------------------------------------------------------------------
__global__ void k_init(float* __restrict__ outp) {
    int i = blockIdx.x * blockDim.x + threadIdx.x;
    if (i < B * VOC) {
        int b = i / VOC, v = i % VOC;
        outp[(size_t)b * TT * VOC + v] = 0.0f;
    }
    if (i < B * DHID) { g_h[0][i] = 0.0f; g_h[1][i] = 0.0f; g_c[i] = 0.0f; }
}

// ---------------------------------------------------------------------------
// Transpose fc_W [VOC][KFC] -> g_fcwt [KFC][VOC] (once)
// ---------------------------------------------------------------------------
__global__ void k_transpose(const float* __restrict__ W) {
    __shared__ float tile[32][33];
    int tx = threadIdx.x, ty = threadIdx.y;          // 32 x 8
    int v0 = blockIdx.x * 32, k0 = blockIdx.y * 32;
    for (int r = ty; r < 32; r += 8) {
        int k = k0 + tx;
        tile[r][tx] = (k < KFC) ? W[(size_t)(v0 + r) * KFC + k] : 0.0f;
    }
    __syncthreads();
    for (int r = ty; r < 32; r += 8) {
        int k = k0 + r;
        if (k < KFC) g_fcwt[(size_t)k * VOC + v0 + tx] = tile[tx][r];
    }
}

// ---------------------------------------------------------------------------
// enc_proj[b,s,j] = attn_b[j] + sum_k enc[b,s,k] * attn_W[128+k][j]   (once)
// ---------------------------------------------------------------------------
__global__ void __launch_bounds__(128) k_encproj(const float* __restrict__ enc,
                                                 const float* __restrict__ attn_W,
                                                 const float* __restrict__ attn_b) {
    __shared__ __align__(16) float es[32 * 8];
    int j = threadIdx.x;
    int row0 = blockIdx.x * 32;
    float acc[32];
    float bj = attn_b[j];
#pragma unroll
    for (int r = 0; r < 32; r++) acc[r] = bj;
    const float* Wenc = attn_W + DHID * DHID;

    for (int k0 = 0; k0 < EHID; k0 += 8) {
        __syncthreads();
        int i0 = j;
        es[i0] = enc[(size_t)(row0 + (i0 >> 3)) * EHID + k0 + (i0 & 7)];
        int i1 = j + 128;
        es[i1] = enc[(size_t)(row0 + (i1 >> 3)) * EHID + k0 + (i1 & 7)];
        __syncthreads();
        float w[8];
#pragma unroll
        for (int kk = 0; kk < 8; kk++) w[kk] = Wenc[(size_t)(k0 + kk) * DHID + j];
#pragma unroll
        for (int r = 0; r < 32; r++) {
            const float4* e4 = (const float4*)(es + r * 8);
            float4 e0 = e4[0], e1 = e4[1];
            acc[r] = fmaf(e0.x, w[0], acc[r]); acc[r] = fmaf(e0.y, w[1], acc[r]);
            acc[r] = fmaf(e0.z, w[2], acc[r]); acc[r] = fmaf(e0.w, w[3], acc[r]);
            acc[r] = fmaf(e1.x, w[4], acc[r]); acc[r] = fmaf(e1.y, w[5], acc[r]);
            acc[r] = fmaf(e1.z, w[6], acc[r]); acc[r] = fmaf(e1.w, w[7], acc[r]);
        }
    }
#pragma unroll
    for (int r = 0; r < 32; r++)
        g_enc_proj[(size_t)(row0 + r) * DHID + j] = acc[r];
}

// ---------------------------------------------------------------------------
// Per-step scores: hp-proj, tanh scores (coalesced, warp-per-s), softmax,
// embedding gather. grid = B, 512 threads (16 warps x 16 s each).
// ---------------------------------------------------------------------------
__global__ void __launch_bounds__(512) k_score(
    const int* __restrict__ trg, const float* __restrict__ embt,
    const float* __restrict__ attn_W, const float* __restrict__ attn_v, int t)
{
    int b = blockIdx.x, tid = threadIdx.x;
    __shared__ float sh_h[DHID], sh_hp[DHID], sh_v[DHID];
    __shared__ float sh_a[S], sh_red[S];

    const float* hold = g_h[t & 1];
    if (tid < DHID) { sh_h[tid] = hold[b * DHID + tid]; sh_v[tid] = attn_v[tid]; }
    __syncthreads();

    // hp[j] = sum_k h[k] * attn_W[k][j]
    if (tid < DHID) {
        float acc = 0.0f;
#pragma unroll 8
        for (int k = 0; k < DHID; k++)
            acc = fmaf(sh_h[k], attn_W[k * DHID + tid], acc);
        sh_hp[tid] = acc;
    }
    __syncthreads();

    // scores: warp w handles s = w*16..w*16+15; lanes cover j (coalesced)
    {
        int w = tid >> 5, lane = tid & 31;
        const float* epb = g_enc_proj + (size_t)b * S * DHID;
        float hp0 = sh_hp[lane],      hp1 = sh_hp[lane + 32];
        float hp2 = sh_hp[lane + 64], hp3 = sh_hp[lane + 96];
        float v0 = sh_v[lane],        v1 = sh_v[lane + 32];
        float v2 = sh_v[lane + 64],   v3 = sh_v[lane + 96];
#pragma unroll 4
        for (int i = 0; i < 16; i++) {
            int s = w * 16 + i;
            const float* ep = epb + (size_t)s * DHID;
            float acc = tanhfast(ep[lane]      + hp0) * v0
                      + tanhfast(ep[lane + 32] + hp1) * v1
                      + tanhfast(ep[lane + 64] + hp2) * v2
                      + tanhfast(ep[lane + 96] + hp3) * v3;
#pragma unroll
            for (int o = 16; o > 0; o >>= 1)
                acc += __shfl_xor_sync(0xFFFFFFFFu, acc, o);
            if (lane == 0) sh_a[s] = acc;
        }
    }
    __syncthreads();

    // softmax over S=256
    if (tid < S) sh_red[tid] = sh_a[tid];
    __syncthreads();
    for (int off = S / 2; off > 0; off >>= 1) {
        if (tid < off) sh_red[tid] = fmaxf(sh_red[tid], sh_red[tid + off]);
        __syncthreads();
    }
    float mx = sh_red[0];
    __syncthreads();
    if (tid < S) { float e = __expf(sh_a[tid] - mx); sh_a[tid] = e; sh_red[tid] = e; }
    __syncthreads();
    for (int off = S / 2; off > 0; off >>= 1) {
        if (tid < off) sh_red[tid] += sh_red[tid + off];
        __syncthreads();
    }
    if (tid < S)
        g_attw[b * S + tid] = sh_a[tid] * __fdividef(1.0f, sh_red[0]);

    // embedding gather -> FC x rows 896..1095 (also LSTM emb input)
    int tok = trg[b * TT + t];
    if (tid < EMBD)
        g_xcatT[(DHID + EHID + tid) * B + b] = embt[(size_t)tok * EMBD + tid];
}

// ---------------------------------------------------------------------------
// Per-step context: weighted[b][d] = sum_s a[s]*enc[b,s,d].
// grid = (EHID/128, B) = (6, 32) = 192 blocks, 128 threads, coalesced.
// ---------------------------------------------------------------------------
__global__ void __launch_bounds__(128) k_ctx(const float* __restrict__ enc) {
    int d = blockIdx.x * 128 + threadIdx.x;
    int b = blockIdx.y;
    __shared__ float sa[S];
    sa[threadIdx.x]       = g_attw[b * S + threadIdx.x];
    sa[threadIdx.x + 128] = g_attw[b * S + threadIdx.x + 128];
    __syncthreads();

    const float* e = enc + (size_t)b * S * EHID + d;
    float a0 = 0.f, a1 = 0.f, a2 = 0.f, a3 = 0.f;
#pragma unroll 8
    for (int s = 0; s < S; s += 4) {
        a0 = fmaf(sa[s],     e[(size_t)s * EHID],       a0);
        a1 = fmaf(sa[s + 1], e[(size_t)(s + 1) * EHID], a1);
        a2 = fmaf(sa[s + 2], e[(size_t)(s + 2) * EHID], a2);
        a3 = fmaf(sa[s + 3], e[(size_t)(s + 3) * EHID], a3);
    }
    g_xcatT[(DHID + d) * B + b] = (a0 + a1) + (a2 + a3);   // FC x rows 128..895
}

// ---------------------------------------------------------------------------
// Per-step LSTM: grid = 64 blocks (2 hid cols each), 256 threads.
// ---------------------------------------------------------------------------
__global__ void __launch_bounds__(256) k_lstm(
    const float* __restrict__ W_ih, const float* __restrict__ W_hh,
    const float* __restrict__ b_ih, const float* __restrict__ b_hh, int t)
{
    int h0 = blockIdx.x * 2;
    int tid = threadIdx.x;
    int gc = tid >> 5;                // 0..7  (gate = gc>>1, col = gc&1)
    int b  = tid & 31;
    int g  = (gc >> 1) * DHID + h0 + (gc & 1);

    __shared__ float sh_hold[32 * 129];
    __shared__ float sg[8][32];

    const float* hold = g_h[t & 1];
    for (int i = tid; i < B * DHID; i += 256) {
        int bb = i >> 7, kk = i & 127;
        sh_hold[bb * 129 + kk] = hold[i];
    }
    __syncthreads();

    float a0 = b_ih[g] + b_hh[g], a1 = 0.f, a2 = 0.f, a3 = 0.f;
    const float* Wg = W_ih + (size_t)g * KLSTM;
    const float* xe = g_xcatT + 896 * B + b;      // emb: x cols 0..199
#pragma unroll 2
    for (int k = 0; k < 200; k += 4) {
        float4 w = *(const float4*)(Wg + k);
        a0 = fmaf(w.x, xe[(k + 0) * B], a0);
        a1 = fmaf(w.y, xe[(k + 1) * B], a1);
        a2 = fmaf(w.z, xe[(k + 2) * B], a2);
        a3 = fmaf(w.w, xe[(k + 3) * B], a3);
    }
    const float* xw = g_xcatT - 72 * B + b;       // weighted: x cols 200..967
#pragma unroll 2
    for (int k = 200; k < KLSTM; k += 4) {
        float4 w = *(const float4*)(Wg + k);
        a0 = fmaf(w.x, xw[(k + 0) * B], a0);
        a1 = fmaf(w.y, xw[(k + 1) * B], a1);
        a2 = fmaf(w.z, xw[(k + 2) * B], a2);
        a3 = fmaf(w.w, xw[(k + 3) * B], a3);
    }
    const float* Wh = W_hh + (size_t)g * DHID;
    const float* hb = sh_hold + b * 129;
#pragma unroll 4
    for (int k = 0; k < DHID; k += 4) {
        float4 w = *(const float4*)(Wh + k);
        a0 = fmaf(w.x, hb[k + 0], a0);
        a1 = fmaf(w.y, hb[k + 1], a1);
        a2 = fmaf(w.z, hb[k + 2], a2);
        a3 = fmaf(w.w, hb[k + 3], a3);
    }
    sg[gc][b] = (a0 + a1) + (a2 + a3);
    __syncthreads();

    if (gc < 2) {
        int col = h0 + gc;
        float gi = sg[0 + gc][b], gf = sg[2 + gc][b];
        float gg = sg[4 + gc][b], go = sg[6 + gc][b];
        float c = g_c[b * DHID + col];
        c = sigfast(gf) * c + sigfast(gi) * tanhfast(gg);
        float h = sigfast(go) * tanhfast(c);
        g_c[b * DHID + col] = c;
        g_h[(t + 1) & 1][b * DHID + col] = h;
        g_xcatT[col * B + b] = h;                 // FC x rows 0..127
    }
}

// ---------------------------------------------------------------------------
// Per-step FC: plain scalar FFMA, thread tile 4v x 8b (32 FMA per 3 LDG).
// grid = 250 blocks x 128 thr. lane -> 4 consecutive v, warp -> 8 batches.
// FMA floor ~62-74us/step; LDG issue (~1/5 of R3) hides under it.
// ---------------------------------------------------------------------------
__global__ void __launch_bounds__(128) k_fc(const float* __restrict__ fc_b,
                                            float* __restrict__ outp, int t) {
    int lane = threadIdx.x & 31;
    int wrp  = threadIdx.x >> 5;
    int v0 = blockIdx.x * 128 + lane * 4;
    int b0 = wrp * 8;

    float acc[8][4];
#pragma unroll
    for (int i = 0; i < 8; i++)
#pragma unroll
        for (int j = 0; j < 4; j++) acc[i][j] = 0.0f;

    const float4* wp = (const float4*)(g_fcwt + v0);
    const float4* xp = (const float4*)(g_xcatT + b0);

#pragma unroll 4
    for (int k = 0; k < KFC; k++) {
        float4 w  = __ldcs(wp + (size_t)k * (VOC / 4));   // streaming weights
        float4 xa = __ldg(xp + k * 8);                     // batches b0..b0+3
        float4 xb = __ldg(xp + k * 8 + 1);                 // batches b0+4..b0+7
        acc[0][0] = fmaf(w.x, xa.x, acc[0][0]); acc[0][1] = fmaf(w.y, xa.x, acc[0][1]);
        acc[0][2] = fmaf(w.z, xa.x, acc[0][2]); acc[0][3] = fmaf(w.w, xa.x, acc[0][3]);
        acc[1][0] = fmaf(w.x, xa.y, acc[1][0]); acc[1][1] = fmaf(w.y, xa.y, acc[1][1]);
        acc[1][2] = fmaf(w.z, xa.y, acc[1][2]); acc[1][3] = fmaf(w.w, xa.y, acc[1][3]);
        acc[2][0] = fmaf(w.x, xa.z, acc[2][0]); acc[2][1] = fmaf(w.y, xa.z, acc[2][1]);
        acc[2][2] = fmaf(w.z, xa.z, acc[2][2]); acc[2][3] = fmaf(w.w, xa.z, acc[2][3]);
        acc[3][0] = fmaf(w.x, xa.w, acc[3][0]); acc[3][1] = fmaf(w.y, xa.w, acc[3][1]);
        acc[3][2] = fmaf(w.z, xa.w, acc[3][2]); acc[3][3] = fmaf(w.w, xa.w, acc[3][3]);
        acc[4][0] = fmaf(w.x, xb.x, acc[4][0]); acc[4][1] = fmaf(w.y, xb.x, acc[4][1]);
        acc[4][2] = fmaf(w.z, xb.x, acc[4][2]); acc[4][3] = fmaf(w.w, xb.x, acc[4][3]);
        acc[5][0] = fmaf(w.x, xb.y, acc[5][0]); acc[5][1] = fmaf(w.y, xb.y, acc[5][1]);
        acc[5][2] = fmaf(w.z, xb.y, acc[5][2]); acc[5][3] = fmaf(w.w, xb.y, acc[5][3]);
        acc[6][0] = fmaf(w.x, xb.z, acc[6][0]); acc[6][1] = fmaf(w.y, xb.z, acc[6][1]);
        acc[6][2] = fmaf(w.z, xb.z, acc[6][2]); acc[6][3] = fmaf(w.w, xb.z, acc[6][3]);
        acc[7][0] = fmaf(w.x, xb.w, acc[7][0]); acc[7][1] = fmaf(w.y, xb.w, acc[7][1]);
        acc[7][2] = fmaf(w.z, xb.w, acc[7][2]); acc[7][3] = fmaf(w.w, xb.w, acc[7][3]);
    }

    float4 bias = *(const float4*)(fc_b + v0);
    float* obase = outp + (size_t)(t + 1) * VOC + v0;
    const size_t bs = (size_t)TT * VOC;
#pragma unroll
    for (int bb = 0; bb < 8; bb++) {
        float4 o = make_float4(acc[bb][0] + bias.x, acc[bb][1] + bias.y,
                               acc[bb][2] + bias.z, acc[bb][3] + bias.w);
        *(float4*)(obase + (size_t)(b0 + bb) * bs) = o;
    }
}

// ---------------------------------------------------------------------------
// Epilogue: argmax over V per (b,t) row
// ---------------------------------------------------------------------------
__global__ void __launch_bounds__(256) k_argmax(const float* __restrict__ outp,
                                                float* __restrict__ tokout) {
    int row = blockIdx.x;
    const float* p = outp + (size_t)row * VOC;
    int tid = threadIdx.x;
    float best = -1e30f;
    int bi = VOC;
    for (int i = tid; i < VOC; i += 256) {
        float vv = p[i];
        if (vv > best || (vv == best && i < bi)) { best = vv; bi = i; }
    }
    __shared__ float sv[256];
    __shared__ int si[256];
    sv[tid] = best; si[tid] = bi;
    __syncthreads();
    for (int off = 128; off > 0; off >>= 1) {
        if (tid < off) {
            float ov = sv[tid + off]; int oi = si[tid + off];
            if (ov > sv[tid] || (ov == sv[tid] && oi < si[tid])) { sv[tid] = ov; si[tid] = oi; }
        }
        __syncthreads();
    }
    if (tid == 0) tokout[row] = (float)si[0];
}

// ---------------------------------------------------------------------------
extern "C" void kernel_launch(void* const* d_in, const int* in_sizes, int n_in,
                              void* d_out, int out_size) {
    const float* enc    = (const float*)d_in[0];
    const int*   trg    = (const int*)d_in[1];
    const float* embt   = (const float*)d_in[2];
    const float* attn_W = (const float*)d_in[3];
    const float* attn_b = (const float*)d_in[4];
    const float* attn_v = (const float*)d_in[5];
    const float* W_ih   = (const float*)d_in[6];
    const float* W_hh   = (const float*)d_in[7];
    const float* b_ih   = (const float*)d_in[8];
    const float* b_hh   = (const float*)d_in[9];
    const float* fc_W   = (const float*)d_in[10];
    const float* fc_b   = (const float*)d_in[11];
    float* outp = (float*)d_out;
    (void)in_sizes; (void)n_in;

    k_init<<<(B * VOC + 255) / 256, 256>>>(outp);
    k_transpose<<<dim3(VOC / 32, (KFC + 31) / 32), dim3(32, 8)>>>(fc_W);
    k_encproj<<<(B * S) / 32, 128>>>(enc, attn_W, attn_b);

    for (int t = 0; t < NSTEP; t++) {
        k_score<<<B, 512>>>(trg, embt, attn_W, attn_v, t);
        k_ctx<<<dim3(EHID / 128, B), 128>>>(enc);
        k_lstm<<<DHID / 2, 256>>>(W_ih, W_hh, b_ih, b_hh, t);
        k_fc<<<VOC / 128, 128>>>(fc_b, outp, t);
    }

    long long need = (long long)B * TT * VOC + (long long)B * TT;
    if ((long long)out_size >= need) {
        k_argmax<<<B * TT, 256>>>(outp, outp + (size_t)B * TT * VOC);
    }
}

// round 7
// speedup vs baseline: 3.2331x; 3.0522x over previous
#include <cuda_runtime.h>
#include <math.h>
#include <stdint.h>

// Problem dims
#define B 32
#define S 256
#define EHID 768
#define DHID 128
#define EMBD 200
#define VOC 32000
#define TT 96
#define NSTEP 95
#define KFC 1096    // DHID + EHID + EMBD
#define KLSTM 968   // EMBD + EHID

// Scratch (static device globals: allowed; no runtime allocation)
__device__ float g_fcwt[(size_t)KFC * VOC];   // fc_W transposed: [k][v], ~140MB
__device__ float g_enc_proj[B * S * DHID];    // 4MB, step-invariant attention term
__device__ float g_xcatT[KFC * B];            // FC input, transposed [k][b]
__device__ float g_attw[B * S];               // softmax attention weights
__device__ float g_h[2][B * DHID];            // ping-pong across steps
__device__ float g_c[B * DHID];

// fast activations (validated: rel_err stayed ~7e-7)
__device__ __forceinline__ float sigfast(float x) {
    return __fdividef(1.0f, 1.0f + __expf(-x));
}
__device__ __forceinline__ float tanhfast(float x) {
    x = fminf(fmaxf(x, -15.0f), 15.0f);
    float e = __expf(2.0f * x);
    return __fdividef(e - 1.0f, e + 1.0f);
}

// cp.async helpers
__device__ __forceinline__ void cpasync16(uint32_t dst, const void* src) {
    asm volatile("cp.async.cg.shared.global [%0], [%1], 16;" :: "r"(dst), "l"(src));
}
__device__ __forceinline__ void cpcommit() {
    asm volatile("cp.async.commit_group;" ::: "memory");
}
template <int N> __device__ __forceinline__ void cpwait() {
    asm volatile("cp.async.wait_group %0;" :: "n"(N) : "memory");
}

// ---------------------------------------------------------------------------
// Init: zero h (both buffers), c, and outputs[:, 0, :]
// ---------------------------------------------------------------------------
__global__ void k_init(float* __restrict__ outp) {
    int i = blockIdx.x * blockDim.x + threadIdx.x;
    if (i < B * VOC) {
        int b = i / VOC, v = i % VOC;
        outp[(size_t)b * TT * VOC + v] = 0.0f;
    }
    if (i < B * DHID) { g_h[0][i] = 0.0f; g_h[1][i] = 0.0f; g_c[i] = 0.0f; }
}

// ---------------------------------------------------------------------------
// Transpose fc_W [VOC][KFC] -> g_fcwt [KFC][VOC] (once)
// ---------------------------------------------------------------------------
__global__ void k_transpose(const float* __restrict__ W) {
    __shared__ float tile[32][33];
    int tx = threadIdx.x, ty = threadIdx.y;          // 32 x 8
    int v0 = blockIdx.x * 32, k0 = blockIdx.y * 32;
    for (int r = ty; r < 32; r += 8) {
        int k = k0 + tx;
        tile[r][tx] = (k < KFC) ? W[(size_t)(v0 + r) * KFC + k] : 0.0f;
    }
    __syncthreads();
    for (int r = ty; r < 32; r += 8) {
        int k = k0 + r;
        if (k < KFC) g_fcwt[(size_t)k * VOC + v0 + tx] = tile[tx][r];
    }
}

// ---------------------------------------------------------------------------
// enc_proj[b,s,j] = attn_b[j] + sum_k enc[b,s,k] * attn_W[128+k][j]   (once)
// ---------------------------------------------------------------------------
__global__ void __launch_bounds__(128) k_encproj(const float* __restrict__ enc,
                                                 const float* __restrict__ attn_W,
                                                 const float* __restrict__ attn_b) {
    __shared__ __align__(16) float es[32 * 8];
    int j = threadIdx.x;
    int row0 = blockIdx.x * 32;
    float acc[32];
    float bj = attn_b[j];
#pragma unroll
    for (int r = 0; r < 32; r++) acc[r] = bj;
    const float* Wenc = attn_W + DHID * DHID;

    for (int k0 = 0; k0 < EHID; k0 += 8) {
        __syncthreads();
        int i0 = j;
        es[i0] = enc[(size_t)(row0 + (i0 >> 3)) * EHID + k0 + (i0 & 7)];
        int i1 = j + 128;
        es[i1] = enc[(size_t)(row0 + (i1 >> 3)) * EHID + k0 + (i1 & 7)];
        __syncthreads();
        float w[8];
#pragma unroll
        for (int kk = 0; kk < 8; kk++) w[kk] = Wenc[(size_t)(k0 + kk) * DHID + j];
#pragma unroll
        for (int r = 0; r < 32; r++) {
            const float4* e4 = (const float4*)(es + r * 8);
            float4 e0 = e4[0], e1 = e4[1];
            acc[r] = fmaf(e0.x, w[0], acc[r]); acc[r] = fmaf(e0.y, w[1], acc[r]);
            acc[r] = fmaf(e0.z, w[2], acc[r]); acc[r] = fmaf(e0.w, w[3], acc[r]);
            acc[r] = fmaf(e1.x, w[4], acc[r]); acc[r] = fmaf(e1.y, w[5], acc[r]);
            acc[r] = fmaf(e1.z, w[6], acc[r]); acc[r] = fmaf(e1.w, w[7], acc[r]);
        }
    }
#pragma unroll
    for (int r = 0; r < 32; r++)
        g_enc_proj[(size_t)(row0 + r) * DHID + j] = acc[r];
}

// ---------------------------------------------------------------------------
// Per-step scores: hp-proj, tanh scores (coalesced), softmax, emb gather.
// grid = B, 512 threads (16 warps x 16 s each).
// ---------------------------------------------------------------------------
__global__ void __launch_bounds__(512) k_score(
    const int* __restrict__ trg, const float* __restrict__ embt,
    const float* __restrict__ attn_W, const float* __restrict__ attn_v, int t)
{
    int b = blockIdx.x, tid = threadIdx.x;
    __shared__ float sh_h[DHID], sh_hp[DHID], sh_v[DHID];
    __shared__ float sh_a[S], sh_red[S];

    const float* hold = g_h[t & 1];
    if (tid < DHID) { sh_h[tid] = hold[b * DHID + tid]; sh_v[tid] = attn_v[tid]; }
    __syncthreads();

    if (tid < DHID) {
        float acc = 0.0f;
#pragma unroll 8
        for (int k = 0; k < DHID; k++)
            acc = fmaf(sh_h[k], attn_W[k * DHID + tid], acc);
        sh_hp[tid] = acc;
    }
    __syncthreads();

    {
        int w = tid >> 5, lane = tid & 31;
        const float* epb = g_enc_proj + (size_t)b * S * DHID;
        float hp0 = sh_hp[lane],      hp1 = sh_hp[lane + 32];
        float hp2 = sh_hp[lane + 64], hp3 = sh_hp[lane + 96];
        float v0 = sh_v[lane],        v1 = sh_v[lane + 32];
        float v2 = sh_v[lane + 64],   v3 = sh_v[lane + 96];
#pragma unroll 4
        for (int i = 0; i < 16; i++) {
            int s = w * 16 + i;
            const float* ep = epb + (size_t)s * DHID;
            float acc = tanhfast(ep[lane]      + hp0) * v0
                      + tanhfast(ep[lane + 32] + hp1) * v1
                      + tanhfast(ep[lane + 64] + hp2) * v2
                      + tanhfast(ep[lane + 96] + hp3) * v3;
#pragma unroll
            for (int o = 16; o > 0; o >>= 1)
                acc += __shfl_xor_sync(0xFFFFFFFFu, acc, o);
            if (lane == 0) sh_a[s] = acc;
        }
    }
    __syncthreads();

    // softmax over S=256
    if (tid < S) sh_red[tid] = sh_a[tid];
    __syncthreads();
    for (int off = S / 2; off > 0; off >>= 1) {
        if (tid < off) sh_red[tid] = fmaxf(sh_red[tid], sh_red[tid + off]);
        __syncthreads();
    }
    float mx = sh_red[0];
    __syncthreads();
    if (tid < S) { float e = __expf(sh_a[tid] - mx); sh_a[tid] = e; sh_red[tid] = e; }
    __syncthreads();
    for (int off = S / 2; off > 0; off >>= 1) {
        if (tid < off) sh_red[tid] += sh_red[tid + off];
        __syncthreads();
    }
    if (tid < S)
        g_attw[b * S + tid] = sh_a[tid] * __fdividef(1.0f, sh_red[0]);

    int tok = trg[b * TT + t];
    if (tid < EMBD)
        g_xcatT[(DHID + EHID + tid) * B + b] = embt[(size_t)tok * EMBD + tid];
}

// ---------------------------------------------------------------------------
// Per-step context: weighted[b][d] = sum_s a[s]*enc[b,s,d].
// grid = (6, 32), 128 threads, coalesced.
// ---------------------------------------------------------------------------
__global__ void __launch_bounds__(128) k_ctx(const float* __restrict__ enc) {
    int d = blockIdx.x * 128 + threadIdx.x;
    int b = blockIdx.y;
    __shared__ float sa[S];
    sa[threadIdx.x]       = g_attw[b * S + threadIdx.x];
    sa[threadIdx.x + 128] = g_attw[b * S + threadIdx.x + 128];
    __syncthreads();

    const float* e = enc + (size_t)b * S * EHID + d;
    float a0 = 0.f, a1 = 0.f, a2 = 0.f, a3 = 0.f;
#pragma unroll 8
    for (int s = 0; s < S; s += 4) {
        a0 = fmaf(sa[s],     e[(size_t)s * EHID],       a0);
        a1 = fmaf(sa[s + 1], e[(size_t)(s + 1) * EHID], a1);
        a2 = fmaf(sa[s + 2], e[(size_t)(s + 2) * EHID], a2);
        a3 = fmaf(sa[s + 3], e[(size_t)(s + 3) * EHID], a3);
    }
    g_xcatT[(DHID + d) * B + b] = (a0 + a1) + (a2 + a3);   // FC x rows 128..895
}

// ---------------------------------------------------------------------------
// Per-step LSTM, 2-way k-split: grid = 128 blocks (1 col each), 256 threads.
// thread = (half, gate, b); halves split the 968-long x dot product.
// ---------------------------------------------------------------------------
__global__ void __launch_bounds__(256) k_lstm(
    const float* __restrict__ W_ih, const float* __restrict__ W_hh,
    const float* __restrict__ b_ih, const float* __restrict__ b_hh, int t)
{
    int col = blockIdx.x;
    int tid = threadIdx.x;
    int half = tid >> 7;
    int gate = (tid >> 5) & 3;
    int b = tid & 31;
    int g = gate * DHID + col;

    __shared__ float sh_hold[32 * 129];
    __shared__ float sg[8][32];

    const float* hold = g_h[t & 1];
    for (int i = tid; i < B * DHID; i += 256)
        sh_hold[(i >> 7) * 129 + (i & 127)] = hold[i];
    __syncthreads();

    const float* Wg = W_ih + (size_t)g * KLSTM;
    float a0 = 0.f, a1 = 0.f, a2 = 0.f, a3 = 0.f;
    if (half == 0) {
        a0 = b_ih[g] + b_hh[g];
        const float* xe = g_xcatT + 896 * B + b;      // emb: x cols 0..199
#pragma unroll 2
        for (int k = 0; k < 200; k += 4) {
            float4 w = *(const float4*)(Wg + k);
            a0 = fmaf(w.x, xe[(k + 0) * B], a0);
            a1 = fmaf(w.y, xe[(k + 1) * B], a1);
            a2 = fmaf(w.z, xe[(k + 2) * B], a2);
            a3 = fmaf(w.w, xe[(k + 3) * B], a3);
        }
        const float* xw = g_xcatT - 72 * B + b;       // weighted: x cols 200..483
#pragma unroll 2
        for (int k = 200; k < 484; k += 4) {
            float4 w = *(const float4*)(Wg + k);
            a0 = fmaf(w.x, xw[(k + 0) * B], a0);
            a1 = fmaf(w.y, xw[(k + 1) * B], a1);
            a2 = fmaf(w.z, xw[(k + 2) * B], a2);
            a3 = fmaf(w.w, xw[(k + 3) * B], a3);
        }
    } else {
        const float* xw = g_xcatT - 72 * B + b;       // weighted: x cols 484..967
#pragma unroll 2
        for (int k = 484; k < 968; k += 4) {
            float4 w = *(const float4*)(Wg + k);
            a0 = fmaf(w.x, xw[(k + 0) * B], a0);
            a1 = fmaf(w.y, xw[(k + 1) * B], a1);
            a2 = fmaf(w.z, xw[(k + 2) * B], a2);
            a3 = fmaf(w.w, xw[(k + 3) * B], a3);
        }
        const float* Wh = W_hh + (size_t)g * DHID;
        const float* hb = sh_hold + b * 129;
#pragma unroll 4
        for (int k = 0; k < DHID; k += 4) {
            float4 w = *(const float4*)(Wh + k);
            a0 = fmaf(w.x, hb[k + 0], a0);
            a1 = fmaf(w.y, hb[k + 1], a1);
            a2 = fmaf(w.z, hb[k + 2], a2);
            a3 = fmaf(w.w, hb[k + 3], a3);
        }
    }
    sg[half * 4 + gate][b] = (a0 + a1) + (a2 + a3);
    __syncthreads();

    if (tid < 32) {
        float gi = sg[0][b] + sg[4][b];
        float gf = sg[1][b] + sg[5][b];
        float gg = sg[2][b] + sg[6][b];
        float go = sg[3][b] + sg[7][b];
        float c = g_c[b * DHID + col];
        c = sigfast(gf) * c + sigfast(gi) * tanhfast(gg);
        float h = sigfast(go) * tanhfast(c);
        g_c[b * DHID + col] = c;
        g_h[(t + 1) & 1][b * DHID + col] = h;
        g_xcatT[col * B + b] = h;                     // FC x rows 0..127
    }
}

// ---------------------------------------------------------------------------
// Per-step FC with cp.async 4-stage pipeline (explicit MLP, latency-proof).
// grid = 250 blocks x 256 thr. Block: 128 v x 32 b.
// Thread: lane -> 4 v, warp -> 4 b (16 accs). Stage = 8 k x 128 v = 4KB.
// 3 stages in flight x 1.7 blk/SM = ~20KB/SM outstanding -> ~5TB/s capable;
// FMA floor ~62-85us/step governs.
// ---------------------------------------------------------------------------
#define FC_KC 8
#define FC_NST 4
#define FC_NSTG (KFC / FC_KC)   // 137

__global__ void __launch_bounds__(256) k_fc(const float* __restrict__ fc_b,
                                            float* __restrict__ outp, int t) {
    __shared__ __align__(16) float sw[FC_NST][FC_KC * 128];
    int tid = threadIdx.x;
    int lane = tid & 31, wrp = tid >> 5;
    int v0 = blockIdx.x * 128;

    // loader: thread covers (k-row r = wrp, 16B chunk = lane) of each stage
    const float* gsrc = g_fcwt + (size_t)wrp * VOC + v0 + lane * 4;
    const size_t gstep = (size_t)FC_KC * VOC;
    uint32_t sdst = (uint32_t)__cvta_generic_to_shared(&sw[0][wrp * 128 + lane * 4]);
    const uint32_t sstage = FC_KC * 128 * 4;

#pragma unroll
    for (int s = 0; s < FC_NST - 1; s++) {
        cpasync16(sdst + s * sstage, gsrc + (size_t)s * gstep);
        cpcommit();
    }

    float acc[4][4];
#pragma unroll
    for (int i = 0; i < 4; i++)
#pragma unroll
        for (int j = 0; j < 4; j++) acc[i][j] = 0.0f;

    const float4* x4 = (const float4*)g_xcatT;   // x[k][b0..b0+3] = x4[k*8 + wrp]

    for (int stg = 0; stg < FC_NSTG; stg++) {
        cpwait<FC_NST - 2>();
        __syncthreads();
        const float* wbuf = sw[stg & (FC_NST - 1)];
#pragma unroll
        for (int r = 0; r < FC_KC; r++) {
            float4 w = *(const float4*)(wbuf + r * 128 + lane * 4);
            float4 x = __ldg(x4 + (size_t)(stg * FC_KC + r) * 8 + wrp);
            acc[0][0] = fmaf(w.x, x.x, acc[0][0]); acc[0][1] = fmaf(w.y, x.x, acc[0][1]);
            acc[0][2] = fmaf(w.z, x.x, acc[0][2]); acc[0][3] = fmaf(w.w, x.x, acc[0][3]);
            acc[1][0] = fmaf(w.x, x.y, acc[1][0]); acc[1][1] = fmaf(w.y, x.y, acc[1][1]);
            acc[1][2] = fmaf(w.z, x.y, acc[1][2]); acc[1][3] = fmaf(w.w, x.y, acc[1][3]);
            acc[2][0] = fmaf(w.x, x.z, acc[2][0]); acc[2][1] = fmaf(w.y, x.z, acc[2][1]);
            acc[2][2] = fmaf(w.z, x.z, acc[2][2]); acc[2][3] = fmaf(w.w, x.z, acc[2][3]);
            acc[3][0] = fmaf(w.x, x.w, acc[3][0]); acc[3][1] = fmaf(w.y, x.w, acc[3][1]);
            acc[3][2] = fmaf(w.z, x.w, acc[3][2]); acc[3][3] = fmaf(w.w, x.w, acc[3][3]);
        }
        int ns = stg + FC_NST - 1;
        if (ns < FC_NSTG)
            cpasync16(sdst + (ns & (FC_NST - 1)) * sstage, gsrc + (size_t)ns * gstep);
        cpcommit();
    }

    int b0 = wrp * 4;
    float4 bias = *(const float4*)(fc_b + v0 + lane * 4);
    float* ob = outp + (size_t)(t + 1) * VOC + v0 + lane * 4;
    const size_t bs = (size_t)TT * VOC;
#pragma unroll
    for (int bb = 0; bb < 4; bb++) {
        float4 o = make_float4(acc[bb][0] + bias.x, acc[bb][1] + bias.y,
                               acc[bb][2] + bias.z, acc[bb][3] + bias.w);
        *(float4*)(ob + (size_t)(b0 + bb) * bs) = o;
    }
}

// ---------------------------------------------------------------------------
// Epilogue: argmax over V per (b,t) row
// ---------------------------------------------------------------------------
__global__ void __launch_bounds__(256) k_argmax(const float* __restrict__ outp,
                                                float* __restrict__ tokout) {
    int row = blockIdx.x;
    const float* p = outp + (size_t)row * VOC;
    int tid = threadIdx.x;
    float best = -1e30f;
    int bi = VOC;
    for (int i = tid; i < VOC; i += 256) {
        float vv = p[i];
        if (vv > best || (vv == best && i < bi)) { best = vv; bi = i; }
    }
    __shared__ float sv[256];
    __shared__ int si[256];
    sv[tid] = best; si[tid] = bi;
    __syncthreads();
    for (int off = 128; off > 0; off >>= 1) {
        if (tid < off) {
            float ov = sv[tid + off]; int oi = si[tid + off];
            if (ov > sv[tid] || (ov == sv[tid] && oi < si[tid])) { sv[tid] = ov; si[tid] = oi; }
        }
        __syncthreads();
    }
    if (tid == 0) tokout[row] = (float)si[0];
}

// ---------------------------------------------------------------------------
extern "C" void kernel_launch(void* const* d_in, const int* in_sizes, int n_in,
                              void* d_out, int out_size) {
    const float* enc    = (const float*)d_in[0];
    const int*   trg    = (const int*)d_in[1];
    const float* embt   = (const float*)d_in[2];
    const float* attn_W = (const float*)d_in[3];
    const float* attn_b = (const float*)d_in[4];
    const float* attn_v = (const float*)d_in[5];
    const float* W_ih   = (const float*)d_in[6];
    const float* W_hh   = (const float*)d_in[7];
    const float* b_ih   = (const float*)d_in[8];
    const float* b_hh   = (const float*)d_in[9];
    const float* fc_W   = (const float*)d_in[10];
    const float* fc_b   = (const float*)d_in[11];
    float* outp = (float*)d_out;
    (void)in_sizes; (void)n_in;

    k_init<<<(B * VOC + 255) / 256, 256>>>(outp);
    k_transpose<<<dim3(VOC / 32, (KFC + 31) / 32), dim3(32, 8)>>>(fc_W);
    k_encproj<<<(B * S) / 32, 128>>>(enc, attn_W, attn_b);

    for (int t = 0; t < NSTEP; t++) {
        k_score<<<B, 512>>>(trg, embt, attn_W, attn_v, t);
        k_ctx<<<dim3(EHID / 128, B), 128>>>(enc);
        k_lstm<<<DHID, 256>>>(W_ih, W_hh, b_ih, b_hh, t);
        k_fc<<<VOC / 128, 256>>>(fc_b, outp, t);
    }

    long long need = (long long)B * TT * VOC + (long long)B * TT;
    if ((long long)out_size >= need) {
        k_argmax<<<B * TT, 256>>>(outp, outp + (size_t)B * TT * VOC);
    }
}